// round 9
// baseline (speedup 1.0000x reference)
#include <cuda_runtime.h>
#include <math.h>

#define BB 32
#define HH 512
#define WW 512
#define CC 3
#define RR 6               // truncated half-width (13 taps)
#define KK 13
#define TT 32              // output tile
#define CW 44              // centered-halo width  (TT + 2*RR)
#define XH 56              // x-halo width         (TT + 4*RR)
#define SPITCH 60          // x smem pitch (mult of 4)
#define SHP 52             // h-blur smem pitch (mult of 4, conflict-free)
#define CPITCH 52          // cent smem pitch (aliases sin_)
#define NTH 256
#define EPS 1e-4f

// 13-tap Gaussian(std=1) weights normalized by the full 19-tap sum.
#define WLIST { 6.0758833e-9f, 1.4867195e-6f, 1.3383022e-4f, 4.4318485e-3f, \
                5.3990967e-2f, 2.4197072e-1f, 3.9894228e-1f, 2.4197072e-1f, \
                5.3990967e-2f, 4.4318485e-3f, 1.3383022e-4f, 1.4867195e-6f, \
                6.0758833e-9f }

// ---------------------------------------------------------------------------
// Fused LCN: one kernel, one 32x32 tile per block, channel loop inside.
// ---------------------------------------------------------------------------
__global__ __launch_bounds__(NTH)
void lcn_fused_kernel(const float* __restrict__ xg,
                      const float* __restrict__ mask,
                      float* __restrict__ out) {
    __shared__ float sin_[XH * SPITCH];   // x halo; later aliased as cent buffer
    __shared__ float sh_[XH * SHP];       // h-blur scratch
    float* cent_ = sin_;                  // cent overlay (44 x CPITCH <= sin_)
    const float W[KK] = WLIST;

    const int tx0 = blockIdx.x * TT;
    const int ty0 = blockIdx.y * TT;
    const int b   = blockIdx.z;
    const int tid  = threadIdx.x;
    const int warp = tid >> 5;
    const int lane = tid & 31;
    const int lx = tid & 31;
    const int yb = (tid >> 5) * 4;

    const float* xb = xg + (size_t)b * HH * WW * CC;
    const bool interior = (blockIdx.x > 0) && (blockIdx.x < 15) &&
                          (blockIdx.y > 0) && (blockIdx.y < 15);

    // task decompositions (computed once)
    const bool h1act = (tid < XH * 4);            // 224 tasks: 12 outs each
    const int  h1row = tid >> 2, h1grp = tid & 3;
    const bool v1act = (tid < 4 * CW);            // 176 tasks: 11 rows each
    const int  v1grp = tid / CW, v1col = tid - (tid / CW) * CW;
    const bool h2act = (tid < CW * 4);            // 176 tasks: 8 outs each
    const int  h2row = tid >> 2, h2grp = tid & 3;

    float res[CC][4];

#pragma unroll 1
    for (int c = 0; c < CC; c++) {
        // ================= x halo load (56x56, deinterleave channel c) =====
        if (interior) {
            for (int row = warp; row < XH; row += 8) {
                const float* rp = xb + ((size_t)(ty0 - 2*RR + row) * WW + (tx0 - 2*RR)) * CC + c;
                float* sp = sin_ + row * SPITCH;
                sp[lane] = rp[3 * lane];
                if (lane < XH - 32) sp[lane + 32] = rp[3 * (lane + 32)];
            }
        } else {
            for (int row = warp; row < XH; row += 8) {
                int gy = ty0 - 2*RR + row;
                bool rv = ((unsigned)gy < HH);
                const float* rp = xb + ((size_t)gy * WW + (tx0 - 2*RR)) * CC + c;
                float* sp = sin_ + row * SPITCH;
#pragma unroll
                for (int s = 0; s < 2; s++) {
                    int xx = lane + s * 32;
                    if (xx < XH) {
                        int gx = tx0 - 2*RR + xx;
                        float v = 0.f;
                        if (rv && (unsigned)gx < WW) v = rp[3 * xx];
                        sp[xx] = v;
                    }
                }
            }
        }
        __syncthreads();

        // ================= hpass1: 56 rows -> 48 cols (44 valid), streaming
        if (h1act) {
            const float4* sp = (const float4*)(sin_ + h1row * SPITCH) + h1grp * 3;
            float acc[12];
#pragma unroll
            for (int o = 0; o < 12; o++) acc[o] = 0.f;
#pragma unroll
            for (int q = 0; q < 6; q++) {
                float4 v4 = sp[q];
                float vv[4] = {v4.x, v4.y, v4.z, v4.w};
#pragma unroll
                for (int u = 0; u < 4; u++) {
                    int k = q * 4 + u;
#pragma unroll
                    for (int o = 0; o < 12; o++) {
                        int j = k - o;
                        if (j >= 0 && j < KK) acc[o] = fmaf(W[j], vv[u], acc[o]);
                    }
                }
            }
            float4* op = (float4*)(sh_ + h1row * SHP) + h1grp * 3;
            op[0] = make_float4(acc[0], acc[1], acc[2],  acc[3]);
            op[1] = make_float4(acc[4], acc[5], acc[6],  acc[7]);
            op[2] = make_float4(acc[8], acc[9], acc[10], acc[11]);
        }
        __syncthreads();

        // ================= vpass1 -> mean -> cent (held in regs) ===========
        float cv[11];
        if (v1act) {
            const int base = v1grp * 11;
            float acc[11];
#pragma unroll
            for (int i = 0; i < 11; i++) acc[i] = 0.f;
#pragma unroll
            for (int k = 0; k < KK + 10; k++) {        // 23 rows
                float v = sh_[(base + k) * SHP + v1col];
#pragma unroll
                for (int i = 0; i < 11; i++) {
                    int j = k - i;
                    if (j >= 0 && j < KK) acc[i] = fmaf(W[j], v, acc[i]);
                }
            }
#pragma unroll
            for (int i = 0; i < 11; i++) {
                float xv = sin_[(base + i + RR) * SPITCH + v1col + RR];
                float cc2 = xv - acc[i];
                if (!interior) {
                    int grow = ty0 - RR + base + i;
                    int gcol = tx0 - RR + v1col;
                    if ((unsigned)grow >= HH || (unsigned)gcol >= WW) cc2 = 0.f;
                }
                cv[i] = cc2;
            }
        }
        __syncthreads();          // sin_ reads done -> safe to overlay cent
        if (v1act) {
            const int base = v1grp * 11;
#pragma unroll
            for (int i = 0; i < 11; i++)
                cent_[(base + i) * CPITCH + v1col] = cv[i];
        }
        __syncthreads();

        // ================= hpass2 on cent^2: 44 rows -> 32 cols ============
        if (h2act) {
            const float4* sp = (const float4*)(cent_ + h2row * CPITCH) + h2grp * 2;
            float acc[8];
#pragma unroll
            for (int o = 0; o < 8; o++) acc[o] = 0.f;
#pragma unroll
            for (int q = 0; q < 5; q++) {
                float4 v4 = sp[q];
                float vv[4] = {v4.x, v4.y, v4.z, v4.w};
#pragma unroll
                for (int u = 0; u < 4; u++) {
                    int k = q * 4 + u;
                    float v = vv[u] * vv[u];
#pragma unroll
                    for (int o = 0; o < 8; o++) {
                        int j = k - o;
                        if (j >= 0 && j < KK) acc[o] = fmaf(W[j], v, acc[o]);
                    }
                }
            }
            float4* op = (float4*)(sh_ + h2row * SHP) + h2grp * 2;
            op[0] = make_float4(acc[0], acc[1], acc[2], acc[3]);
            op[1] = make_float4(acc[4], acc[5], acc[6], acc[7]);
        }
        __syncthreads();

        // ================= vpass2 -> var -> res ============================
        {
            float acc0 = 0.f, acc1 = 0.f, acc2 = 0.f, acc3 = 0.f;
#pragma unroll
            for (int k = 0; k < KK + 3; k++) {
                float v = sh_[(yb + k) * SHP + lx];
                if (k - 0 >= 0 && k - 0 < KK) acc0 = fmaf(W[k - 0], v, acc0);
                if (k - 1 >= 0 && k - 1 < KK) acc1 = fmaf(W[k - 1], v, acc1);
                if (k - 2 >= 0 && k - 2 < KK) acc2 = fmaf(W[k - 2], v, acc2);
                if (k - 3 >= 0 && k - 3 < KK) acc3 = fmaf(W[k - 3], v, acc3);
            }
            res[c][0] = __fdividef(cent_[(yb + 0 + RR) * CPITCH + lx + RR], sqrtf(acc0) + EPS);
            res[c][1] = __fdividef(cent_[(yb + 1 + RR) * CPITCH + lx + RR], sqrtf(acc1) + EPS);
            res[c][2] = __fdividef(cent_[(yb + 2 + RR) * CPITCH + lx + RR], sqrtf(acc2) + EPS);
            res[c][3] = __fdividef(cent_[(yb + 3 + RR) * CPITCH + lx + RR], sqrtf(acc3) + EPS);
        }
        __syncthreads();          // protect smem before next channel's load
    }

    // ================= mask + interleaved output ===========================
#pragma unroll
    for (int r = 0; r < 4; r++) {
        int gy = ty0 + yb + r;
        int gx = tx0 + lx;
        float m = mask[(size_t)(b * HH + gy) * WW + gx];
        size_t o = ((size_t)(b * HH + gy) * WW + gx) * CC;
        out[o + 0] = res[0][r] * m;
        out[o + 1] = res[1][r] * m;
        out[o + 2] = res[2][r] * m;
    }
}

// ---------------------------------------------------------------------------
extern "C" void kernel_launch(void* const* d_in, const int* in_sizes, int n_in,
                              void* d_out, int out_size) {
    const float* x0   = (const float*)d_in[0];
    const float* mask = (const float*)d_in[1];
    float* out = (float*)d_out;

    dim3 grid(WW / TT, HH / TT, BB);
    lcn_fused_kernel<<<grid, NTH>>>(x0, mask, out);
}

// round 10
// speedup vs baseline: 1.9669x; 1.9669x over previous
#include <cuda_runtime.h>
#include <math.h>

#define BB 32
#define HH 512
#define WW 512
#define CC 3
#define RR 6              // truncated half-width (13 taps)
#define KK 13
#define TT 32             // output tile
#define HL (TT + 2*RR)    // 44
#define SPITCH 52         // smem input pitch (floats, mult of 4 for float4)
#define HPITCH 36         // h-out pitch (floats, mult of 4)
#define NTH 256
#define EPS 1e-4f

// padded centered scratch: rows 6+512+6=524, row stride 528, origin (6,6).
// Borders never written -> stay zero (device globals are zero-initialized).
#define PH 524
#define PW 528

// 13-tap Gaussian(std=1) weights normalized by the full 19-tap sum.
#define WLIST { 6.0758833e-9f, 1.4867195e-6f, 1.3383022e-4f, 4.4318485e-3f, \
                5.3990967e-2f, 2.4197072e-1f, 3.9894228e-1f, 2.4197072e-1f, \
                5.3990967e-2f, 4.4318485e-3f, 1.3383022e-4f, 1.4867195e-6f, \
                6.0758833e-9f }

__device__ float g_cent[(size_t)BB * CC * PH * PW];

// ---------------------------------------------------------------------------
// Horizontal pass: 176 tasks (44 rows x 4 groups of 8 outputs).
// STREAMING: each float4 is consumed by FMAs immediately (no staging array)
// to keep live registers ~13 instead of ~32.
// ---------------------------------------------------------------------------
template<bool SQ>
__device__ __forceinline__ void hpass(const float* __restrict__ sin_,
                                      float* __restrict__ sh_, int tid) {
    const float W[KK] = WLIST;
    if (tid < HL * 4) {
        int row = tid >> 2;
        int grp = tid & 3;
        const float4* sp = (const float4*)(sin_ + row * SPITCH) + grp * 2;
        float acc[8];
#pragma unroll
        for (int o = 0; o < 8; o++) acc[o] = 0.f;
#pragma unroll
        for (int q = 0; q < 5; q++) {             // 20 floats -> 8 outputs
            float4 v4 = sp[q];
            float vv[4] = {v4.x, v4.y, v4.z, v4.w};
#pragma unroll
            for (int u = 0; u < 4; u++) {
                int k = q * 4 + u;
                float v = SQ ? vv[u] * vv[u] : vv[u];
#pragma unroll
                for (int o = 0; o < 8; o++) {
                    int j = k - o;
                    if (j >= 0 && j < KK) acc[o] = fmaf(W[j], v, acc[o]);
                }
            }
        }
        float4* op = (float4*)(sh_ + row * HPITCH) + grp * 2;
        op[0] = make_float4(acc[0], acc[1], acc[2], acc[3]);
        op[1] = make_float4(acc[4], acc[5], acc[6], acc[7]);
    }
}

// ---------------------------------------------------------------------------
// Kernel 1: centered = x0 - blur(x0); writes interior of padded g_cent.
// ---------------------------------------------------------------------------
__global__ __launch_bounds__(NTH)
void lcn_mean_kernel(const float* __restrict__ xg) {
    __shared__ float sin_[HL * SPITCH];
    __shared__ float sh_[HL * HPITCH];
    const float W[KK] = WLIST;

    const int tx0 = blockIdx.x * TT;
    const int ty0 = blockIdx.y * TT;
    const int b   = blockIdx.z;
    const int tid  = threadIdx.x;
    const int warp = tid >> 5;
    const int lane = tid & 31;
    const int lx = tid & 31;
    const int yb = (tid >> 5) * 4;

    const float* xb = xg + (size_t)b * HH * WW * CC;
    const bool interior = (blockIdx.x > 0) && (blockIdx.x < 15) &&
                          (blockIdx.y > 0) && (blockIdx.y < 15);

#pragma unroll 1
    for (int c = 0; c < CC; c++) {
        if (interior) {
            // predicate-free halo load (deinterleave channel c)
            for (int row = warp; row < HL; row += 8) {
                const float* rp = xb + ((size_t)(ty0 - RR + row) * WW + (tx0 - RR)) * CC + c;
                float* sp = sin_ + row * SPITCH;
                sp[lane] = rp[3 * lane];
                if (lane < HL - 32) sp[lane + 32] = rp[3 * (lane + 32)];
            }
        } else {
            for (int row = warp; row < HL; row += 8) {
                int gy = ty0 - RR + row;
                bool rv = ((unsigned)gy < HH);
                const float* rp = xb + ((size_t)gy * WW + (tx0 - RR)) * CC + c;
                float* sp = sin_ + row * SPITCH;
#pragma unroll
                for (int s = 0; s < 2; s++) {
                    int xx = lane + s * 32;
                    if (xx < HL) {
                        int gx = tx0 - RR + xx;
                        float v = 0.f;
                        if (rv && (unsigned)gx < WW) v = rp[3 * xx];
                        sp[xx] = v;
                    }
                }
            }
        }
        __syncthreads();

        hpass<false>(sin_, sh_, tid);
        __syncthreads();

        // vertical pass: column lx, rows yb..yb+3
        float acc0 = 0.f, acc1 = 0.f, acc2 = 0.f, acc3 = 0.f;
#pragma unroll
        for (int k = 0; k < KK + 3; k++) {
            float v = sh_[(yb + k) * HPITCH + lx];
            if (k - 0 >= 0 && k - 0 < KK) acc0 = fmaf(W[k - 0], v, acc0);
            if (k - 1 >= 0 && k - 1 < KK) acc1 = fmaf(W[k - 1], v, acc1);
            if (k - 2 >= 0 && k - 2 < KK) acc2 = fmaf(W[k - 2], v, acc2);
            if (k - 3 >= 0 && k - 3 < KK) acc3 = fmaf(W[k - 3], v, acc3);
        }
        // store to padded g_cent (origin 6,6), coalesced
        float* cb = g_cent + ((size_t)(b * CC + c) * PH + (ty0 + yb + RR)) * PW
                    + (tx0 + lx + RR);
        cb[0 * (size_t)PW] = sin_[(yb + 0 + RR) * SPITCH + lx + RR] - acc0;
        cb[1 * (size_t)PW] = sin_[(yb + 1 + RR) * SPITCH + lx + RR] - acc1;
        cb[2 * (size_t)PW] = sin_[(yb + 2 + RR) * SPITCH + lx + RR] - acc2;
        cb[3 * (size_t)PW] = sin_[(yb + 3 + RR) * SPITCH + lx + RR] - acc3;
        __syncthreads();
    }
}

// ---------------------------------------------------------------------------
// Kernel 2: var = blur(centered^2); out = centered/(sqrt(var)+eps) * mask
// ---------------------------------------------------------------------------
__global__ __launch_bounds__(NTH)
void lcn_out_kernel(const float* __restrict__ mask, float* __restrict__ out) {
    __shared__ float sin_[HL * SPITCH];   // unsquared centered halo
    __shared__ float sh_[HL * HPITCH];
    const float W[KK] = WLIST;

    const int tx0 = blockIdx.x * TT;
    const int ty0 = blockIdx.y * TT;
    const int b   = blockIdx.z;
    const int tid = threadIdx.x;
    const int lx = tid & 31;
    const int yb = (tid >> 5) * 4;

    float res[CC][4];

#pragma unroll 1
    for (int c = 0; c < CC; c++) {
        // halo load: pure float4 copies, no bounds checks (zero-padded gmem).
        // 44 rows x 12 float4 (48 floats: halo 44 + 4 over-read, in-bounds).
        for (int f = tid; f < HL * 12; f += NTH) {
            int row = f / 12;
            int seg = f - row * 12;
            const float4* gp = (const float4*)(g_cent +
                ((size_t)(b * CC + c) * PH + (ty0 + row)) * PW) + 8 * blockIdx.x;
            *((float4*)(sin_ + row * SPITCH) + seg) = gp[seg];
        }
        __syncthreads();

        hpass<true>(sin_, sh_, tid);   // squares on the fly
        __syncthreads();

        // vertical pass -> var -> res
        float acc0 = 0.f, acc1 = 0.f, acc2 = 0.f, acc3 = 0.f;
#pragma unroll
        for (int k = 0; k < KK + 3; k++) {
            float v = sh_[(yb + k) * HPITCH + lx];
            if (k - 0 >= 0 && k - 0 < KK) acc0 = fmaf(W[k - 0], v, acc0);
            if (k - 1 >= 0 && k - 1 < KK) acc1 = fmaf(W[k - 1], v, acc1);
            if (k - 2 >= 0 && k - 2 < KK) acc2 = fmaf(W[k - 2], v, acc2);
            if (k - 3 >= 0 && k - 3 < KK) acc3 = fmaf(W[k - 3], v, acc3);
        }
        res[c][0] = __fdividef(sin_[(yb + 0 + RR) * SPITCH + lx + RR], sqrtf(acc0) + EPS);
        res[c][1] = __fdividef(sin_[(yb + 1 + RR) * SPITCH + lx + RR], sqrtf(acc1) + EPS);
        res[c][2] = __fdividef(sin_[(yb + 2 + RR) * SPITCH + lx + RR], sqrtf(acc2) + EPS);
        res[c][3] = __fdividef(sin_[(yb + 3 + RR) * SPITCH + lx + RR], sqrtf(acc3) + EPS);
        __syncthreads();
    }

    // mask + interleaved output
#pragma unroll
    for (int r = 0; r < 4; r++) {
        int gy = ty0 + yb + r;
        int gx = tx0 + lx;
        float m = mask[(size_t)(b * HH + gy) * WW + gx];
        size_t o = ((size_t)(b * HH + gy) * WW + gx) * CC;
        out[o + 0] = res[0][r] * m;
        out[o + 1] = res[1][r] * m;
        out[o + 2] = res[2][r] * m;
    }
}

// ---------------------------------------------------------------------------
extern "C" void kernel_launch(void* const* d_in, const int* in_sizes, int n_in,
                              void* d_out, int out_size) {
    const float* x0   = (const float*)d_in[0];
    const float* mask = (const float*)d_in[1];
    float* out = (float*)d_out;

    dim3 grid(WW / TT, HH / TT, BB);
    lcn_mean_kernel<<<grid, NTH>>>(x0);
    lcn_out_kernel<<<grid, NTH>>>(mask, out);
}